// round 5
// baseline (speedup 1.0000x reference)
#include <cuda_runtime.h>
#include <math.h>
#include <stdint.h>

#define Bv 8
#define Hv 256
#define Pv 1024
#define Kv 32
#define Ev 4
#define BNv 64
#define W1S 516

#define KP 264            // padded K: 256 nbr + 4 edge + 4 zeros
#define NS 33             // k8 steps
#define AS 268            // A row stride (floats) -> conflict-free frag/pooled LDS

// smem float offsets
#define A_FLOATS (128*AS)            // 34304
#define CI_W2    A_FLOATS            // 64
#define CI_CT    (CI_W2 + 64)        // 4*64
#define CI_SPART (CI_CT + 256)       // 4*32
#define CI_WGT   (CI_SPART + 128)    // 4*32
#define SMEM_FLOATS (CI_WGT + 128)
#define SMEM_BYTES  (SMEM_FLOATS * 4)   // 139520

__device__ float    g_curterm[Bv * Pv * BNv];
__device__ uint32_t g_w1frag[NS * 32 * 16];   // fragment-ordered tf32 B (w1n|w1e|0)

static __device__ __forceinline__ uint32_t cvt_tf32(float x) {
    uint32_t r;
    asm("cvt.rna.tf32.f32 %0, %1;" : "=r"(r) : "f"(x));
    return r;
}

#define MMA_TF32(D, A0, A1, A2, A3, B0, B1)                                   \
    asm volatile(                                                             \
        "mma.sync.aligned.m16n8k8.row.col.f32.tf32.tf32.f32 "                 \
        "{%0,%1,%2,%3},{%4,%5,%6,%7},{%8,%9},{%0,%1,%2,%3};"                  \
        : "+f"((D)[0]), "+f"((D)[1]), "+f"((D)[2]), "+f"((D)[3])              \
        : "r"(A0), "r"(A1), "r"(A2), "r"(A3), "r"(B0), "r"(B1))

// ---------------------------------------------------------------------------
// Kernel 0: build fragment-ordered tf32 B from w1 (cols: 0..255 w1n, 256..259 w1e, pad 0)
// element (s, lane, nt, reg): c = s*8 + (lane&3) + reg*4 ; o = nt*8 + (lane>>2)
// ---------------------------------------------------------------------------
__global__ __launch_bounds__(256) void prep_kernel(const float* __restrict__ w1)
{
    int idx = blockIdx.x * 256 + threadIdx.x;
    if (idx >= NS * 32 * 16) return;
    int reg  = idx & 1;
    int nt   = (idx >> 1) & 7;
    int lane = (idx >> 4) & 31;
    int s    = idx >> 9;
    int c = s * 8 + (lane & 3) + reg * 4;
    int o = nt * 8 + (lane >> 2);
    float v = 0.f;
    if (c < 256)      v = w1[o * W1S + 256 + c];
    else if (c < 260) v = w1[o * W1S + 512 + (c - 256)];
    g_w1frag[((s * 32 + lane) * 8 + nt) * 2 + reg] = cvt_tf32(v);
}

// ---------------------------------------------------------------------------
// Kernel 1: cur_term[b,p,o] = sum_c current[b,c,p] * w1[o,c] + b1[o]   (exact fp32)
// ---------------------------------------------------------------------------
__global__ __launch_bounds__(256) void curterm_kernel(
    const float* __restrict__ cur,
    const float* __restrict__ w1,
    const float* __restrict__ b1)
{
    const int blk = blockIdx.x;
    const int b  = blk >> 4;
    const int p0 = (blk & 15) << 6;
    const int t  = threadIdx.x;
    const int po = t & 63;
    const int og = t >> 6;

    __shared__ float s_cur[64 * 64];
    __shared__ float s_w[64 * 68];

    float acc[16];
#pragma unroll
    for (int i = 0; i < 16; ++i) acc[i] = 0.f;

    for (int c0 = 0; c0 < Hv; c0 += 64) {
        __syncthreads();
#pragma unroll
        for (int i = 0; i < 16; ++i) {
            int idx = t + i * 256;
            int c = idx >> 6, pp = idx & 63;
            s_cur[c * 64 + pp] = cur[((size_t)(b * Hv + c0 + c)) * Pv + p0 + pp];
        }
#pragma unroll
        for (int i = 0; i < 16; ++i) {
            int idx = t + i * 256;
            int o = idx >> 6, c = idx & 63;
            s_w[c * 68 + o] = w1[o * W1S + c0 + c];
        }
        __syncthreads();
#pragma unroll 4
        for (int cc = 0; cc < 64; ++cc) {
            float x = s_cur[cc * 64 + po];
            const float4* wr = (const float4*)&s_w[cc * 68 + og * 16];
#pragma unroll
            for (int j = 0; j < 4; ++j) {
                float4 w4 = wr[j];
                acc[j * 4 + 0] += x * w4.x;
                acc[j * 4 + 1] += x * w4.y;
                acc[j * 4 + 2] += x * w4.z;
                acc[j * 4 + 3] += x * w4.w;
            }
        }
    }
    float* dst = &g_curterm[((size_t)b * Pv + p0 + po) * BNv + og * 16];
#pragma unroll
    for (int j = 0; j < 4; ++j) {
        float4 v;
        v.x = acc[j*4+0] + b1[og*16 + j*4 + 0];
        v.y = acc[j*4+1] + b1[og*16 + j*4 + 1];
        v.z = acc[j*4+2] + b1[og*16 + j*4 + 2];
        v.w = acc[j*4+3] + b1[og*16 + j*4 + 3];
        *(float4*)&dst[j*4] = v;
    }
}

// ---------------------------------------------------------------------------
// Kernel 2: fused attention via mma.sync m16n8k8 tf32.
// CTA = 4 p's. A[row=(p,k)][c] fp32 in smem (stride 268); B from g_w1frag.
// Warp w: rows w*16..w*16+15 (p = w>>1, k-half = w&1), all 64 o.
// ---------------------------------------------------------------------------
__global__ __launch_bounds__(256, 1) void attn_kernel(
    const float* __restrict__ nbr,
    const float* __restrict__ vld,
    const float* __restrict__ edg,
    const float* __restrict__ w2,
    const float* __restrict__ b2,
    float* __restrict__ out)
{
    extern __shared__ float sm[];
    const int t = threadIdx.x;
    const int w = t >> 5;
    const int lane = t & 31;
    const int b  = blockIdx.x >> 8;
    const int p0 = (blockIdx.x & 255) << 2;

    // ---- stage A: 264 tasks = (pl, c-quad q); warp-task -> 4 coalesced LDG + STS.128
#pragma unroll 1
    for (int it = 0; it < 33; ++it) {
        int tau = it * 8 + w;
        int pl = tau & 3, q = tau >> 2;
        int pg = p0 + pl;
        float4 v;
        if (q < 64) {
            const float* s0 = nbr + (((size_t)(b * Hv + q * 4)) * Pv + pg) * Kv + lane;
            v.x = s0[0];
            v.y = s0[(size_t)Pv * Kv];
            v.z = s0[2 * (size_t)Pv * Kv];
            v.w = s0[3 * (size_t)Pv * Kv];
        } else if (q == 64) {
            const float* s0 = edg + (((size_t)(b * Ev)) * Pv + pg) * Kv + lane;
            v.x = s0[0];
            v.y = s0[(size_t)Pv * Kv];
            v.z = s0[2 * (size_t)Pv * Kv];
            v.w = s0[3 * (size_t)Pv * Kv];
        } else {
            v.x = v.y = v.z = v.w = 0.f;
        }
        *(float4*)&sm[(pl * 32 + lane) * AS + q * 4] = v;
    }
    // ---- stage ctrl: w2, curterm ----
    if (t < 64) sm[CI_W2 + t] = w2[t];
    {
        int pl = t >> 6, o = t & 63;
        sm[CI_CT + t] = g_curterm[((size_t)b * Pv + p0 + pl) * BNv + o];
    }
    __syncthreads();

    // ---- main GEMM ----
    const int wrow = w * 16;
    float d[8][4];
#pragma unroll
    for (int i = 0; i < 8; ++i)
#pragma unroll
        for (int j = 0; j < 4; ++j) d[i][j] = 0.f;

    const float* arow = &sm[(wrow + (lane >> 2)) * AS + (lane & 3)];

#pragma unroll 3
    for (int s = 0; s < NS; ++s) {
        const float* ap = arow + s * 8;
        uint32_t a0 = cvt_tf32(ap[0]);
        uint32_t a2 = cvt_tf32(ap[4]);
        uint32_t a1 = cvt_tf32(ap[8 * AS]);
        uint32_t a3 = cvt_tf32(ap[8 * AS + 4]);
        const uint4* bp = (const uint4*)&g_w1frag[(s * 32 + lane) * 16];
        uint4 q0 = bp[0], q1 = bp[1], q2 = bp[2], q3 = bp[3];
        MMA_TF32(d[0], a0, a1, a2, a3, q0.x, q0.y);
        MMA_TF32(d[1], a0, a1, a2, a3, q0.z, q0.w);
        MMA_TF32(d[2], a0, a1, a2, a3, q1.x, q1.y);
        MMA_TF32(d[3], a0, a1, a2, a3, q1.z, q1.w);
        MMA_TF32(d[4], a0, a1, a2, a3, q2.x, q2.y);
        MMA_TF32(d[5], a0, a1, a2, a3, q2.z, q2.w);
        MMA_TF32(d[6], a0, a1, a2, a3, q3.x, q3.y);
        MMA_TF32(d[7], a0, a1, a2, a3, q3.z, q3.w);
    }

    // ---- epilogue: relu(D + ct) . w2 -> logits per row; rows = lane>>2, +8 ----
    {
        const int p = w >> 1, kb = (w & 1) * 16;
        float lg0 = 0.f, lg1 = 0.f;
#pragma unroll
        for (int nt = 0; nt < 8; ++nt) {
#pragma unroll
            for (int j = 0; j < 2; ++j) {
                int o = nt * 8 + (lane & 3) * 2 + j;
                float ctv = sm[CI_CT + p * 64 + o];
                float w2v = sm[CI_W2 + o];
                lg0 += fmaxf(d[nt][j]     + ctv, 0.f) * w2v;
                lg1 += fmaxf(d[nt][2 + j] + ctv, 0.f) * w2v;
            }
        }
        lg0 += __shfl_xor_sync(0xffffffffu, lg0, 1);
        lg0 += __shfl_xor_sync(0xffffffffu, lg0, 2);
        lg1 += __shfl_xor_sync(0xffffffffu, lg1, 1);
        lg1 += __shfl_xor_sync(0xffffffffu, lg1, 2);
        if ((lane & 3) == 0) {
            int r = lane >> 2;
            sm[CI_SPART + p * 32 + kb + r]     = lg0;
            sm[CI_SPART + p * 32 + kb + r + 8] = lg1;
        }
    }
    __syncthreads();

    // ---- masked softmax: threads 0..127, warp = p, lane = k ----
    if (t < 128) {
        int p = w, k = lane;
        float logit = sm[CI_SPART + p * 32 + k] + __ldg(b2);
        bool valid = vld[(((size_t)b * Pv) + p0 + p) * Kv + k] > 0.5f;
        unsigned msk = __ballot_sync(0xffffffffu, valid);
        const float NEG_INF = __int_as_float(0xff800000);
        float l = valid ? logit : NEG_INF;
        float m = l;
#pragma unroll
        for (int dd = 16; dd; dd >>= 1) m = fmaxf(m, __shfl_xor_sync(0xffffffffu, m, dd));
        float e = (msk != 0u) ? expf(l - m) : 0.f;
        float ssum = e;
#pragma unroll
        for (int dd = 16; dd; dd >>= 1) ssum += __shfl_xor_sync(0xffffffffu, ssum, dd);
        sm[CI_WGT + p * 32 + k] = (msk != 0u) ? (e / ssum) : 0.f;
    }
    __syncthreads();

    // ---- pooled: thread = c (0..255), exact fp32 A; float4 store over 4 p ----
    {
        const int c = t;
        float accp[4];
#pragma unroll
        for (int pp = 0; pp < 4; ++pp) {
            float a = 0.f;
#pragma unroll 8
            for (int k = 0; k < 32; ++k)
                a = fmaf(sm[(pp * 32 + k) * AS + c], sm[CI_WGT + pp * 32 + k], a);
            accp[pp] = a;
        }
        float4 o4 = {accp[0], accp[1], accp[2], accp[3]};
        *(float4*)&out[((size_t)b * Hv + c) * Pv + p0] = o4;
    }
}

// ---------------------------------------------------------------------------
extern "C" void kernel_launch(void* const* d_in, const int* in_sizes, int n_in,
                              void* d_out, int out_size)
{
    const float* cur = (const float*)d_in[0];
    const float* nbr = (const float*)d_in[1];
    const float* vld = (const float*)d_in[2];
    const float* edg = (const float*)d_in[3];
    const float* w1  = (const float*)d_in[4];
    const float* b1  = (const float*)d_in[5];
    const float* w2  = (const float*)d_in[6];
    const float* b2  = (const float*)d_in[7];
    float* out = (float*)d_out;

    prep_kernel<<<66, 256>>>(w1);
    curterm_kernel<<<128, 256>>>(cur, w1, b1);

    cudaFuncSetAttribute(attn_kernel,
                         cudaFuncAttributeMaxDynamicSharedMemorySize, SMEM_BYTES);
    attn_kernel<<<Bv * (Pv / 4), 256, SMEM_BYTES>>>(nbr, vld, edg, w2, b2, out);
}

// round 6
// speedup vs baseline: 1.7219x; 1.7219x over previous
#include <cuda_runtime.h>
#include <math.h>
#include <stdint.h>

#define Bv 8
#define Hv 256
#define Pv 1024
#define Kv 32
#define Ev 4
#define BNv 64
#define W1S 516

#define NS 33             // k8 steps (264 = 256 nbr + 4 edge + 4 zero)
#define AS 268            // A row stride (== 4 mod 8 -> frag/pooled LDS conflict-free)

// smem float offsets (M = 64 rows = 2p x 32k)
#define A_FLOATS (64*AS)             // 17152
#define CI_W2    A_FLOATS            // 64
#define CI_CT    (CI_W2 + 64)        // 2*64  [pl][o]
#define CI_SPART (CI_CT + 128)       // 2*64  [half][row]
#define CI_WGT   (CI_SPART + 128)    // 64    [pl][k]
#define SMEM_BYTES 79872             // padded > 76K: caps occupancy at 2 CTAs/SM

__device__ float    g_curterm[Bv * Pv * BNv];
__device__ uint32_t g_w1frag[NS * 32 * 16];   // fragment-ordered tf32 B (w1n|w1e|0)

static __device__ __forceinline__ uint32_t cvt_tf32(float x) {
    uint32_t r;
    asm("cvt.rna.tf32.f32 %0, %1;" : "=r"(r) : "f"(x));
    return r;
}
static __device__ __forceinline__ uint32_t s2u(const void* p) {
    uint32_t a;
    asm("{ .reg .u64 t; cvta.to.shared.u64 t, %1; cvt.u32.u64 %0, t; }"
        : "=r"(a) : "l"(p));
    return a;
}
static __device__ __forceinline__ void cp_async4(uint32_t dst, const void* src) {
    asm volatile("cp.async.ca.shared.global [%0], [%1], 4;"
                 :: "r"(dst), "l"(src) : "memory");
}

#define MMA_TF32(D, A0, A1, A2, A3, B0, B1)                                   \
    asm volatile(                                                             \
        "mma.sync.aligned.m16n8k8.row.col.f32.tf32.tf32.f32 "                 \
        "{%0,%1,%2,%3},{%4,%5,%6,%7},{%8,%9},{%0,%1,%2,%3};"                  \
        : "+f"((D)[0]), "+f"((D)[1]), "+f"((D)[2]), "+f"((D)[3])              \
        : "r"(A0), "r"(A1), "r"(A2), "r"(A3), "r"(B0), "r"(B1))

// ---------------------------------------------------------------------------
// Kernel 0: fragment-ordered tf32 B from w1 (c: 0..255 w1n, 256..259 w1e, pad 0)
// element (s, lane, nt, reg): c = s*8 + (lane&3) + reg*4 ; o = nt*8 + (lane>>2)
// ---------------------------------------------------------------------------
__global__ __launch_bounds__(256) void prep_kernel(const float* __restrict__ w1)
{
    int idx = blockIdx.x * 256 + threadIdx.x;
    if (idx >= NS * 32 * 16) return;
    int reg  = idx & 1;
    int nt   = (idx >> 1) & 7;
    int lane = (idx >> 4) & 31;
    int s    = idx >> 9;
    int c = s * 8 + (lane & 3) + reg * 4;
    int o = nt * 8 + (lane >> 2);
    float v = 0.f;
    if (c < 256)      v = w1[o * W1S + 256 + c];
    else if (c < 260) v = w1[o * W1S + 512 + (c - 256)];
    g_w1frag[((s * 32 + lane) * 8 + nt) * 2 + reg] = cvt_tf32(v);
}

// ---------------------------------------------------------------------------
// Kernel 1: cur_term[b,p,o] = sum_c current[b,c,p] * w1[o,c] + b1[o]  (fp32)
// ---------------------------------------------------------------------------
__global__ __launch_bounds__(256) void curterm_kernel(
    const float* __restrict__ cur,
    const float* __restrict__ w1,
    const float* __restrict__ b1)
{
    const int blk = blockIdx.x;
    const int b  = blk >> 4;
    const int p0 = (blk & 15) << 6;
    const int t  = threadIdx.x;
    const int po = t & 63;
    const int og = t >> 6;

    __shared__ float s_cur[64 * 64];
    __shared__ float s_w[64 * 68];

    float acc[16];
#pragma unroll
    for (int i = 0; i < 16; ++i) acc[i] = 0.f;

    for (int c0 = 0; c0 < Hv; c0 += 64) {
        __syncthreads();
#pragma unroll
        for (int i = 0; i < 16; ++i) {
            int idx = t + i * 256;
            int c = idx >> 6, pp = idx & 63;
            s_cur[c * 64 + pp] = cur[((size_t)(b * Hv + c0 + c)) * Pv + p0 + pp];
        }
#pragma unroll
        for (int i = 0; i < 16; ++i) {
            int idx = t + i * 256;
            int o = idx >> 6, c = idx & 63;
            s_w[c * 68 + o] = w1[o * W1S + c0 + c];
        }
        __syncthreads();
#pragma unroll 4
        for (int cc = 0; cc < 64; ++cc) {
            float x = s_cur[cc * 64 + po];
            const float4* wr = (const float4*)&s_w[cc * 68 + og * 16];
#pragma unroll
            for (int j = 0; j < 4; ++j) {
                float4 w4 = wr[j];
                acc[j * 4 + 0] += x * w4.x;
                acc[j * 4 + 1] += x * w4.y;
                acc[j * 4 + 2] += x * w4.z;
                acc[j * 4 + 3] += x * w4.w;
            }
        }
    }
    float* dst = &g_curterm[((size_t)b * Pv + p0 + po) * BNv + og * 16];
#pragma unroll
    for (int j = 0; j < 4; ++j) {
        float4 v;
        v.x = acc[j*4+0] + b1[og*16 + j*4 + 0];
        v.y = acc[j*4+1] + b1[og*16 + j*4 + 1];
        v.z = acc[j*4+2] + b1[og*16 + j*4 + 2];
        v.w = acc[j*4+3] + b1[og*16 + j*4 + 3];
        *(float4*)&dst[j*4] = v;
    }
}

// ---------------------------------------------------------------------------
// Kernel 2: fused attention via mma.sync m16n8k8 tf32.
// CTA = 2 p's (M=64 rows=(p,k)). A fp32 in smem (stride 268), cp.async staged.
// Warp w: rows (w&3)*16..+15, N-half h=w>>2 (32 o's).
// ---------------------------------------------------------------------------
__global__ __launch_bounds__(256) void attn_kernel(
    const float* __restrict__ nbr,
    const float* __restrict__ vld,
    const float* __restrict__ edg,
    const float* __restrict__ w2,
    const float* __restrict__ b2,
    float* __restrict__ out)
{
    extern __shared__ float sm[];
    const uint32_t sbase = s2u(sm);
    const int t = threadIdx.x;
    const int w = t >> 5;
    const int lane = t & 31;
    const int b  = blockIdx.x >> 9;
    const int p0 = (blockIdx.x & 511) << 1;

    // ---- stage A via cp.async: warp task (pl = w&1 fixed, c = w/2 + 4i) ----
    {
        const int pl = w & 1;
        const int cb = w >> 1;           // starting c
        const int pg = p0 + pl;
        const float* src = nbr + (((size_t)(b * Hv + cb)) * Pv + pg) * Kv + lane;
        uint32_t dst = sbase + (uint32_t)(((pl * 32 + lane) * AS + cb) * 4);
        const size_t sstep = (size_t)4 * Pv * Kv;
#pragma unroll 8
        for (int i = 0; i < 64; ++i) {          // c = cb + 4i  (0..255)
            cp_async4(dst, src);
            src += sstep;
            dst += 16;
        }
        // c = 256 + cb : edge column e = cb
        const float* esrc = edg + (((size_t)(b * Ev + cb)) * Pv + pg) * Kv + lane;
        cp_async4(dst, esrc);
        // c = 260 + cb : zero pad
        sm[(pl * 32 + lane) * AS + 260 + cb] = 0.f;
    }
    // ---- stage ctrl: w2, curterm ----
    if (t < 64) sm[CI_W2 + t] = w2[t];
    if (t < 128) {
        int pl = t >> 6, o = t & 63;
        sm[CI_CT + t] = g_curterm[((size_t)b * Pv + p0 + pl) * BNv + o];
    }
    asm volatile("cp.async.commit_group;" ::: "memory");
    asm volatile("cp.async.wait_group 0;" ::: "memory");
    __syncthreads();

    // ---- main GEMM: warp = (row-quarter, N-half) ----
    const int wrow = (w & 3) * 16;
    const int h = w >> 2;

    float d[4][4];
#pragma unroll
    for (int i = 0; i < 4; ++i)
#pragma unroll
        for (int j = 0; j < 4; ++j) d[i][j] = 0.f;

    const float* arow = &sm[(wrow + (lane >> 2)) * AS + (lane & 3)];
    const uint4* __restrict__ bfr =
        (const uint4*)&g_w1frag[(size_t)lane * 16 + h * 8];

#pragma unroll 3
    for (int s = 0; s < NS; ++s) {
        const float* ap = arow + s * 8;
        uint32_t a0 = cvt_tf32(ap[0]);
        uint32_t a2 = cvt_tf32(ap[4]);
        uint32_t a1 = cvt_tf32(ap[8 * AS]);
        uint32_t a3 = cvt_tf32(ap[8 * AS + 4]);
        uint4 q0 = bfr[s * 128];        // (s*32 lanes *16 u32)/4 = s*128 uint4s
        uint4 q1 = bfr[s * 128 + 1];
        MMA_TF32(d[0], a0, a1, a2, a3, q0.x, q0.y);
        MMA_TF32(d[1], a0, a1, a2, a3, q0.z, q0.w);
        MMA_TF32(d[2], a0, a1, a2, a3, q1.x, q1.y);
        MMA_TF32(d[3], a0, a1, a2, a3, q1.z, q1.w);
    }

    // ---- epilogue: relu(D + ct) . w2 -> per-row partial logits (this N-half)
    {
        const int pl = (w & 3) >> 1;     // rows 0..31 -> p0, 32..63 -> p0+1
        float lg0 = 0.f, lg1 = 0.f;
#pragma unroll
        for (int nt = 0; nt < 4; ++nt) {
#pragma unroll
            for (int j = 0; j < 2; ++j) {
                int o = h * 32 + nt * 8 + (lane & 3) * 2 + j;
                float ctv = sm[CI_CT + pl * 64 + o];
                float w2v = sm[CI_W2 + o];
                lg0 += fmaxf(d[nt][j]     + ctv, 0.f) * w2v;
                lg1 += fmaxf(d[nt][2 + j] + ctv, 0.f) * w2v;
            }
        }
        lg0 += __shfl_xor_sync(0xffffffffu, lg0, 1);
        lg0 += __shfl_xor_sync(0xffffffffu, lg0, 2);
        lg1 += __shfl_xor_sync(0xffffffffu, lg1, 1);
        lg1 += __shfl_xor_sync(0xffffffffu, lg1, 2);
        if ((lane & 3) == 0) {
            int r0 = wrow + (lane >> 2);
            sm[CI_SPART + h * 64 + r0]     = lg0;
            sm[CI_SPART + h * 64 + r0 + 8] = lg1;
        }
    }
    __syncthreads();

    // ---- masked softmax: threads 0..63, warp = pl, lane = k ----
    if (t < 64) {
        int pl = t >> 5, k = t & 31;
        float logit = sm[CI_SPART + t] + sm[CI_SPART + 64 + t] + __ldg(b2);
        bool valid = vld[(((size_t)b * Pv) + p0 + pl) * Kv + k] > 0.5f;
        unsigned msk = __ballot_sync(0xffffffffu, valid);
        const float NEG_INF = __int_as_float(0xff800000);
        float l = valid ? logit : NEG_INF;
        float m = l;
#pragma unroll
        for (int dd = 16; dd; dd >>= 1) m = fmaxf(m, __shfl_xor_sync(0xffffffffu, m, dd));
        float e = (msk != 0u) ? expf(l - m) : 0.f;
        float ssum = e;
#pragma unroll
        for (int dd = 16; dd; dd >>= 1) ssum += __shfl_xor_sync(0xffffffffu, ssum, dd);
        sm[CI_WGT + t] = (msk != 0u) ? (e / ssum) : 0.f;
    }
    __syncthreads();

    // ---- pooled: thread = c, exact fp32 A; float2 store over 2 p ----
    {
        const int c = t;
        float a0 = 0.f, a1 = 0.f;
#pragma unroll 8
        for (int k = 0; k < 32; ++k) {
            a0 = fmaf(sm[k * AS + c],        sm[CI_WGT + k],      a0);
            a1 = fmaf(sm[(32 + k) * AS + c], sm[CI_WGT + 32 + k], a1);
        }
        float2 o2 = {a0, a1};
        *(float2*)&out[((size_t)b * Hv + c) * Pv + p0] = o2;
    }
}

// ---------------------------------------------------------------------------
extern "C" void kernel_launch(void* const* d_in, const int* in_sizes, int n_in,
                              void* d_out, int out_size)
{
    const float* cur = (const float*)d_in[0];
    const float* nbr = (const float*)d_in[1];
    const float* vld = (const float*)d_in[2];
    const float* edg = (const float*)d_in[3];
    const float* w1  = (const float*)d_in[4];
    const float* b1  = (const float*)d_in[5];
    const float* w2  = (const float*)d_in[6];
    const float* b2  = (const float*)d_in[7];
    float* out = (float*)d_out;

    prep_kernel<<<66, 256>>>(w1);
    curterm_kernel<<<128, 256>>>(cur, w1, b1);

    cudaFuncSetAttribute(attn_kernel,
                         cudaFuncAttributeMaxDynamicSharedMemorySize, SMEM_BYTES);
    attn_kernel<<<Bv * (Pv / 2), 256, SMEM_BYTES>>>(nbr, vld, edg, w2, b2, out);
}

// round 8
// speedup vs baseline: 3.0119x; 1.7492x over previous
#include <cuda_runtime.h>
#include <math.h>
#include <stdint.h>

#define Bv 8
#define Hv 256
#define Pv 1024
#define Kv 32
#define Ev 4
#define BNv 64
#define W1S 516

#define NS 33             // k8 steps (264 = 256 nbr + 4 edge + 4 zero)
#define SAs 72            // A row stride in floats (72 % 32 == 8 -> frag LDS bijective banks)

// smem float offsets. A: [c=0..263][col = pl*32 + k], stride SAs
#define A_FLOATS (264*SAs)           // 19008
#define CI_W2    A_FLOATS            // 64
#define CI_CT    (CI_W2 + 64)        // 2*64  [pl][o]
#define CI_SPART (CI_CT + 128)       // 2*64  [half][row]
#define CI_WGT   (CI_SPART + 128)    // 64    [pl][k]
#define SMEM_FLOATS (CI_WGT + 64)
#define SMEM_BYTES  (SMEM_FLOATS * 4)   // 77824 -> 2 CTAs/SM, L1D ~76KB

__device__ float    g_curterm[Bv * Pv * BNv];
__device__ uint32_t g_w1frag[NS * 512];   // [s][h][qsel][lane][j] coalesced tf32 B frags

static __device__ __forceinline__ uint32_t cvt_tf32(float x) {
    uint32_t r;
    asm("cvt.rna.tf32.f32 %0, %1;" : "=r"(r) : "f"(x));
    return r;
}
static __device__ __forceinline__ uint32_t s2u(const void* p) {
    uint32_t a;
    asm("{ .reg .u64 t; cvta.to.shared.u64 t, %1; cvt.u32.u64 %0, t; }"
        : "=r"(a) : "l"(p));
    return a;
}
static __device__ __forceinline__ void cp_async16(uint32_t dst, const void* src) {
    asm volatile("cp.async.cg.shared.global [%0], [%1], 16;"
                 :: "r"(dst), "l"(src) : "memory");
}

#define MMA_TF32(D, A0, A1, A2, A3, B0, B1)                                   \
    asm volatile(                                                             \
        "mma.sync.aligned.m16n8k8.row.col.f32.tf32.tf32.f32 "                 \
        "{%0,%1,%2,%3},{%4,%5,%6,%7},{%8,%9},{%0,%1,%2,%3};"                  \
        : "+f"((D)[0]), "+f"((D)[1]), "+f"((D)[2]), "+f"((D)[3])              \
        : "r"(A0), "r"(A1), "r"(A2), "r"(A3), "r"(B0), "r"(B1))

// ---------------------------------------------------------------------------
// Kernel 0: coalesced fragment-ordered tf32 B from w1.
// u32 index = s*512 + h*256 + qsel*128 + lane*4 + j
//   nt = h*4 + qsel*2 + (j>>1); reg = j&1
//   o = nt*8 + (lane>>2); c = s*8 + (lane&3) + reg*4
// ---------------------------------------------------------------------------
__global__ __launch_bounds__(256) void prep_kernel(const float* __restrict__ w1)
{
    int idx = blockIdx.x * 256 + threadIdx.x;
    if (idx >= NS * 512) return;
    int j    = idx & 3;
    int lane = (idx >> 2) & 31;
    int qsel = (idx >> 7) & 1;
    int h    = (idx >> 8) & 1;
    int s    = idx >> 9;
    int nt  = h * 4 + qsel * 2 + (j >> 1);
    int reg = j & 1;
    int o = nt * 8 + (lane >> 2);
    int c = s * 8 + (lane & 3) + reg * 4;
    float v = 0.f;
    if (c < 256)      v = w1[o * W1S + 256 + c];
    else if (c < 260) v = w1[o * W1S + 512 + (c - 256)];
    g_w1frag[idx] = cvt_tf32(v);
}

// ---------------------------------------------------------------------------
// Kernel 1: cur_term[b,p,o] = sum_c current[b,c,p] * w1[o,c] + b1[o]  (fp32)
// ---------------------------------------------------------------------------
__global__ __launch_bounds__(256) void curterm_kernel(
    const float* __restrict__ cur,
    const float* __restrict__ w1,
    const float* __restrict__ b1)
{
    const int blk = blockIdx.x;
    const int b  = blk >> 4;
    const int p0 = (blk & 15) << 6;
    const int t  = threadIdx.x;
    const int po = t & 63;
    const int og = t >> 6;

    __shared__ float s_cur[64 * 64];
    __shared__ float s_w[64 * 68];

    float acc[16];
#pragma unroll
    for (int i = 0; i < 16; ++i) acc[i] = 0.f;

    for (int c0 = 0; c0 < Hv; c0 += 64) {
        __syncthreads();
#pragma unroll
        for (int i = 0; i < 16; ++i) {
            int idx = t + i * 256;
            int c = idx >> 6, pp = idx & 63;
            s_cur[c * 64 + pp] = cur[((size_t)(b * Hv + c0 + c)) * Pv + p0 + pp];
        }
#pragma unroll
        for (int i = 0; i < 16; ++i) {
            int idx = t + i * 256;
            int o = idx >> 6, c = idx & 63;
            s_w[c * 68 + o] = w1[o * W1S + c0 + c];
        }
        __syncthreads();
#pragma unroll 4
        for (int cc = 0; cc < 64; ++cc) {
            float x = s_cur[cc * 64 + po];
            const float4* wr = (const float4*)&s_w[cc * 68 + og * 16];
#pragma unroll
            for (int j = 0; j < 4; ++j) {
                float4 w4 = wr[j];
                acc[j * 4 + 0] += x * w4.x;
                acc[j * 4 + 1] += x * w4.y;
                acc[j * 4 + 2] += x * w4.z;
                acc[j * 4 + 3] += x * w4.w;
            }
        }
    }
    float* dst = &g_curterm[((size_t)b * Pv + p0 + po) * BNv + og * 16];
#pragma unroll
    for (int j = 0; j < 4; ++j) {
        float4 v;
        v.x = acc[j*4+0] + b1[og*16 + j*4 + 0];
        v.y = acc[j*4+1] + b1[og*16 + j*4 + 1];
        v.z = acc[j*4+2] + b1[og*16 + j*4 + 2];
        v.w = acc[j*4+3] + b1[og*16 + j*4 + 3];
        *(float4*)&dst[j*4] = v;
    }
}

// ---------------------------------------------------------------------------
// Kernel 2: fused attention via mma.sync m16n8k8 tf32.
// CTA = 2 p's. A smem layout: [c][pl*32+k], stride 72 (c-major, no transpose!).
// Warp w: row-quarter (w&3)*16, N-half h=w>>2.
// ---------------------------------------------------------------------------
__global__ __launch_bounds__(256, 2) void attn_kernel(
    const float* __restrict__ nbr,
    const float* __restrict__ vld,
    const float* __restrict__ edg,
    const float* __restrict__ w2,
    const float* __restrict__ b2,
    float* __restrict__ out)
{
    extern __shared__ float sm[];
    const uint32_t sbase = s2u(sm);
    const int t = threadIdx.x;
    const int w = t >> 5;
    const int lane = t & 31;
    const int b  = blockIdx.x >> 9;
    const int p0 = (blockIdx.x & 511) << 1;

    // ---- stage A: 132 warp-tasks (c-quad x pl); 16B cp.async per lane ----
    {
        const int sub   = lane >> 3;     // which c within the quad
        const int chunk = lane & 7;      // 16B chunk within the 128B row
#pragma unroll
        for (int i = 0; i < 17; ++i) {
            int gi = i * 8 + w;
            if (gi >= 132) break;
            int pl = gi & 1, cq = gi >> 1;
            int c = cq * 4 + sub;
            uint32_t dst = sbase + (uint32_t)(c * (SAs*4) + pl * 128 + chunk * 16);
            if (c < 256) {
                const float* src = nbr + (((size_t)(b * Hv + c)) * Pv + p0 + pl) * Kv
                                 + chunk * 4;
                cp_async16(dst, src);
            } else if (c < 260) {
                const float* src = edg + (((size_t)(b * Ev + (c - 256))) * Pv + p0 + pl) * Kv
                                 + chunk * 4;
                cp_async16(dst, src);
            } else {
                float4 z = {0.f, 0.f, 0.f, 0.f};
                *(float4*)&sm[c * SAs + pl * 32 + chunk * 4] = z;
            }
        }
    }
    // ---- stage ctrl: w2, curterm ----
    if (t < 64) sm[CI_W2 + t] = w2[t];
    if (t < 128) {
        int pl = t >> 6, o = t & 63;
        sm[CI_CT + t] = g_curterm[((size_t)b * Pv + p0 + pl) * BNv + o];
    }
    asm volatile("cp.async.commit_group;" ::: "memory");
    asm volatile("cp.async.wait_group 0;" ::: "memory");
    __syncthreads();

    // ---- main GEMM ----
    const int wrow = (w & 3) * 16;
    const int h = w >> 2;

    float d[4][4];
#pragma unroll
    for (int i = 0; i < 4; ++i)
#pragma unroll
        for (int j = 0; j < 4; ++j) d[i][j] = 0.f;

    // A frag: addr = c*SAs + row;  c = s*8 + (lane&3), row = wrow + (lane>>2)
    const float* acol = &sm[(lane & 3) * SAs + wrow + (lane >> 2)];
    const uint4* __restrict__ bp0 = (const uint4*)g_w1frag + (size_t)(h * 2) * 32 + lane;

#pragma unroll 3
    for (int s = 0; s < NS; ++s) {
        const float* ap = acol + s * 8 * SAs;
        uint32_t a0 = cvt_tf32(ap[0]);           // (row, c)
        uint32_t a1 = cvt_tf32(ap[8]);           // (row+8, c)
        uint32_t a2 = cvt_tf32(ap[4 * SAs]);     // (row, c+4)
        uint32_t a3 = cvt_tf32(ap[4 * SAs + 8]); // (row+8, c+4)
        uint4 q0 = bp0[(size_t)s * 128];         // coalesced: lane*16B in 512B block
        uint4 q1 = bp0[(size_t)s * 128 + 32];
        MMA_TF32(d[0], a0, a1, a2, a3, q0.x, q0.y);
        MMA_TF32(d[1], a0, a1, a2, a3, q0.z, q0.w);
        MMA_TF32(d[2], a0, a1, a2, a3, q1.x, q1.y);
        MMA_TF32(d[3], a0, a1, a2, a3, q1.z, q1.w);
    }

    // ---- epilogue: relu(D + ct) . w2 -> per-row partial logits (this N-half)
    {
        const int pl = (w & 3) >> 1;     // rows 0..31 -> p0, 32..63 -> p0+1
        float lg0 = 0.f, lg1 = 0.f;
#pragma unroll
        for (int nt = 0; nt < 4; ++nt) {
#pragma unroll
            for (int j = 0; j < 2; ++j) {
                int o = h * 32 + nt * 8 + (lane & 3) * 2 + j;
                float ctv = sm[CI_CT + pl * 64 + o];
                float w2v = sm[CI_W2 + o];
                lg0 += fmaxf(d[nt][j]     + ctv, 0.f) * w2v;
                lg1 += fmaxf(d[nt][2 + j] + ctv, 0.f) * w2v;
            }
        }
        lg0 += __shfl_xor_sync(0xffffffffu, lg0, 1);
        lg0 += __shfl_xor_sync(0xffffffffu, lg0, 2);
        lg1 += __shfl_xor_sync(0xffffffffu, lg1, 1);
        lg1 += __shfl_xor_sync(0xffffffffu, lg1, 2);
        if ((lane & 3) == 0) {
            int r0 = wrow + (lane >> 2);
            sm[CI_SPART + h * 64 + r0]     = lg0;
            sm[CI_SPART + h * 64 + r0 + 8] = lg1;
        }
    }
    __syncthreads();

    // ---- masked softmax: threads 0..63, warp = pl, lane = k ----
    if (t < 64) {
        int pl = t >> 5, k = t & 31;
        float logit = sm[CI_SPART + t] + sm[CI_SPART + 64 + t] + __ldg(b2);
        bool valid = vld[(((size_t)b * Pv) + p0 + pl) * Kv + k] > 0.5f;
        unsigned msk = __ballot_sync(0xffffffffu, valid);
        const float NEG_INF = __int_as_float(0xff800000);
        float l = valid ? logit : NEG_INF;
        float m = l;
#pragma unroll
        for (int dd = 16; dd; dd >>= 1) m = fmaxf(m, __shfl_xor_sync(0xffffffffu, m, dd));
        float e = (msk != 0u) ? expf(l - m) : 0.f;
        float ssum = e;
#pragma unroll
        for (int dd = 16; dd; dd >>= 1) ssum += __shfl_xor_sync(0xffffffffu, ssum, dd);
        sm[CI_WGT + t] = (msk != 0u) ? (e / ssum) : 0.f;
    }
    __syncthreads();

    // ---- pooled: thread = c, row-major float4 reads; float2 store over 2 p ----
    {
        const float* row = &sm[t * SAs];
        float a0 = 0.f, a1 = 0.f;
#pragma unroll
        for (int q = 0; q < 8; ++q) {
            float4 v0 = *(const float4*)&row[q * 4];          // pl 0
            float4 v1 = *(const float4*)&row[32 + q * 4];     // pl 1
            float4 w0 = *(const float4*)&sm[CI_WGT + q * 4];
            float4 w1v = *(const float4*)&sm[CI_WGT + 32 + q * 4];
            a0 += v0.x * w0.x + v0.y * w0.y + v0.z * w0.z + v0.w * w0.w;
            a1 += v1.x * w1v.x + v1.y * w1v.y + v1.z * w1v.z + v1.w * w1v.w;
        }
        float2 o2 = {a0, a1};
        *(float2*)&out[((size_t)b * Hv + t) * Pv + p0] = o2;
    }
}

// ---------------------------------------------------------------------------
extern "C" void kernel_launch(void* const* d_in, const int* in_sizes, int n_in,
                              void* d_out, int out_size)
{
    const float* cur = (const float*)d_in[0];
    const float* nbr = (const float*)d_in[1];
    const float* vld = (const float*)d_in[2];
    const float* edg = (const float*)d_in[3];
    const float* w1  = (const float*)d_in[4];
    const float* b1  = (const float*)d_in[5];
    const float* w2  = (const float*)d_in[6];
    const float* b2  = (const float*)d_in[7];
    float* out = (float*)d_out;

    prep_kernel<<<66, 256>>>(w1);
    curterm_kernel<<<128, 256>>>(cur, w1, b1);

    cudaFuncSetAttribute(attn_kernel,
                         cudaFuncAttributeMaxDynamicSharedMemorySize, SMEM_BYTES);
    attn_kernel<<<Bv * (Pv / 2), 256, SMEM_BYTES>>>(nbr, vld, edg, w2, b2, out);
}